// round 5
// baseline (speedup 1.0000x reference)
#include <cuda_runtime.h>
#include <cuda_bf16.h>

#define NMAX  100000
#define EMAX  1600000
#define D_IN  128
#define D_OUT 32

__device__ float g_h [NMAX * D_OUT];
__device__ float g_w2[NMAX];
__device__ int   g_cnt[NMAX];
__device__ int   g_off[NMAX + 1];
__device__ int   g_cur[NMAX];
__device__ int   g_bsum[256];
__device__ unsigned long long g_sorted[EMAX];

__device__ __forceinline__ unsigned long long fma2(
    unsigned long long a, unsigned long long b, unsigned long long c)
{
    unsigned long long d;
    asm("fma.rn.f32x2 %0, %1, %2, %3;" : "=l"(d) : "l"(a), "l"(b), "l"(c));
    return d;
}

__device__ __forceinline__ unsigned long long pack2(float x)
{
    unsigned long long d;
    asm("mov.b64 %0, {%1, %1};" : "=l"(d) : "f"(x));
    return d;
}

// ---------------------------------------------------------------------------
// GEMM: h = relu(X @ W) + w2 precompute.
// 128 threads/block, 128-row tile. Thread = 8 rows x 4 cols (16 FMA2/k).
// Xs transposed + XOR-swizzled: phys(k,r) = k*128 + 4*((r>>2)^(k>>2)) + (r&3)
// ---------------------------------------------------------------------------
__global__ __launch_bounds__(128, 4) void gemm_relu_kernel(
    const float* __restrict__ X, const float* __restrict__ W,
    const int* __restrict__ arrive, const float* __restrict__ dw2,
    const int* __restrict__ obs_ptr, int n)
{
    __shared__ float Xs[32 * 128];
    __shared__ float Ws[128 * 32];

    const int tid = threadIdx.x;
    const int rowbase = blockIdx.x * 128;

    // per-node w2 = dw2[60*obs - arrive - 1]
    {
        const int node = rowbase + tid;
        if (node < n) {
            const int obs = obs_ptr ? __ldg(obs_ptr) : 60;
            const int idx = 60 * obs - __ldg(arrive + node) - 1;
            g_w2[node] = __ldg(dw2 + idx);
        }
    }

    const float4* X4 = reinterpret_cast<const float4*>(X);
    const int lc = tid & 7;              // loader k-float4 within chunk
    const int lrow = tid >> 3;           // loader base row (stride 16)

    // prefetch chunk 0: 8 float4 per thread (rows lrow + s*16)
    float4 pf[8];
    #pragma unroll
    for (int s = 0; s < 8; s++) {
        const int rr = lrow + s * 16;
        float4 v = make_float4(0.f, 0.f, 0.f, 0.f);
        if (rowbase + rr < n) v = X4[(size_t)(rowbase + rr) * 32 + lc];
        pf[s] = v;
    }

    // load W (1024 float4 / 128 threads = 8 each)
    const float4* W4 = reinterpret_cast<const float4*>(W);
    float4* Ws4 = reinterpret_cast<float4*>(Ws);
    #pragma unroll
    for (int i = tid; i < 1024; i += 128) Ws4[i] = W4[i];

    const int rowgrp = tid >> 3;         // 0..15 -> rows rowgrp*8..+7
    const int c0 = (tid & 7) * 4;        // cols c0..c0+3
    const int b0 = rowgrp * 2;           // 4-row block index

    unsigned long long acc[4][4];        // [row-pair][col]
    #pragma unroll
    for (int rp = 0; rp < 4; rp++)
        #pragma unroll
        for (int j = 0; j < 4; j++) acc[rp][j] = 0ULL;

    #pragma unroll 1
    for (int chunk = 0; chunk < 4; chunk++) {
        // store prefetched tile (transposed + swizzled)
        #pragma unroll
        for (int s = 0; s < 8; s++) {
            const int rr = lrow + s * 16;
            const int base = 4 * ((rr >> 2) ^ lc) + (rr & 3);
            Xs[(4 * lc + 0) * 128 + base] = pf[s].x;
            Xs[(4 * lc + 1) * 128 + base] = pf[s].y;
            Xs[(4 * lc + 2) * 128 + base] = pf[s].z;
            Xs[(4 * lc + 3) * 128 + base] = pf[s].w;
        }
        __syncthreads();

        if (chunk < 3) {
            #pragma unroll
            for (int s = 0; s < 8; s++) {
                const int rr = lrow + s * 16;
                float4 v = make_float4(0.f, 0.f, 0.f, 0.f);
                if (rowbase + rr < n)
                    v = X4[(size_t)(rowbase + rr) * 32 + (chunk + 1) * 8 + lc];
                pf[s] = v;
            }
        }

        #pragma unroll 4
        for (int kl = 0; kl < 32; kl++) {
            const int m = kl >> 2;
            const ulonglong2 xa = *reinterpret_cast<const ulonglong2*>(
                &Xs[kl * 128 + (((b0)     ^ m) << 2)]);   // rows 8rg..8rg+3
            const ulonglong2 xb = *reinterpret_cast<const ulonglong2*>(
                &Xs[kl * 128 + (((b0 + 1) ^ m) << 2)]);   // rows 8rg+4..+7

            const int kg = chunk * 32 + kl;
            const float4 w = *reinterpret_cast<const float4*>(&Ws[kg * 32 + c0]);
            const unsigned long long wp0 = pack2(w.x);
            const unsigned long long wp1 = pack2(w.y);
            const unsigned long long wp2 = pack2(w.z);
            const unsigned long long wp3 = pack2(w.w);

            acc[0][0] = fma2(xa.x, wp0, acc[0][0]);
            acc[0][1] = fma2(xa.x, wp1, acc[0][1]);
            acc[0][2] = fma2(xa.x, wp2, acc[0][2]);
            acc[0][3] = fma2(xa.x, wp3, acc[0][3]);
            acc[1][0] = fma2(xa.y, wp0, acc[1][0]);
            acc[1][1] = fma2(xa.y, wp1, acc[1][1]);
            acc[1][2] = fma2(xa.y, wp2, acc[1][2]);
            acc[1][3] = fma2(xa.y, wp3, acc[1][3]);
            acc[2][0] = fma2(xb.x, wp0, acc[2][0]);
            acc[2][1] = fma2(xb.x, wp1, acc[2][1]);
            acc[2][2] = fma2(xb.x, wp2, acc[2][2]);
            acc[2][3] = fma2(xb.x, wp3, acc[2][3]);
            acc[3][0] = fma2(xb.y, wp0, acc[3][0]);
            acc[3][1] = fma2(xb.y, wp1, acc[3][1]);
            acc[3][2] = fma2(xb.y, wp2, acc[3][2]);
            acc[3][3] = fma2(xb.y, wp3, acc[3][3]);
        }
        __syncthreads();
    }

    // epilogue: unpack, relu, store 8 rows x 4 cols
    #pragma unroll
    for (int rp = 0; rp < 4; rp++) {
        float lo[4], hi[4];
        #pragma unroll
        for (int j = 0; j < 4; j++) {
            float l, h;
            asm("mov.b64 {%0, %1}, %2;" : "=f"(l), "=f"(h) : "l"(acc[rp][j]));
            lo[j] = fmaxf(l, 0.f);
            hi[j] = fmaxf(h, 0.f);
        }
        const int grl = rowbase + rowgrp * 8 + 2 * rp;
        if (grl < n)
            *reinterpret_cast<float4*>(&g_h[grl * D_OUT + c0]) =
                make_float4(lo[0], lo[1], lo[2], lo[3]);
        if (grl + 1 < n)
            *reinterpret_cast<float4*>(&g_h[(grl + 1) * D_OUT + c0]) =
                make_float4(hi[0], hi[1], hi[2], hi[3]);
    }
}

// ---------------------------------------------------------------------------
// Histogram of edge_row (4 edges per thread)
// ---------------------------------------------------------------------------
__global__ __launch_bounds__(256) void hist_kernel(
    const int* __restrict__ erow, int E)
{
    const int i = blockIdx.x * 256 + threadIdx.x;
    const int e0 = i * 4;
    if (e0 + 3 < E) {
        const int4 r = reinterpret_cast<const int4*>(erow)[i];
        atomicAdd(&g_cnt[r.x], 1);
        atomicAdd(&g_cnt[r.y], 1);
        atomicAdd(&g_cnt[r.z], 1);
        atomicAdd(&g_cnt[r.w], 1);
    } else {
        for (int e = e0; e < E; e++) atomicAdd(&g_cnt[erow[e]], 1);
    }
}

// ---------------------------------------------------------------------------
// Scan pass 1: per-block (1024 items) totals
// ---------------------------------------------------------------------------
__global__ __launch_bounds__(256) void scan_totals_kernel(int n)
{
    __shared__ int red[8];
    const int t = threadIdx.x;
    const int base = blockIdx.x * 1024 + t * 4;

    int s = 0;
    if (base + 3 < n) {
        const int4 v = *reinterpret_cast<const int4*>(&g_cnt[base]);
        s = v.x + v.y + v.z + v.w;
    } else {
        for (int j = 0; j < 4; j++)
            if (base + j < n) s += g_cnt[base + j];
    }
    // warp reduce
    #pragma unroll
    for (int d = 16; d > 0; d >>= 1) s += __shfl_xor_sync(0xffffffffu, s, d);
    if ((t & 31) == 0) red[t >> 5] = s;
    __syncthreads();
    if (t == 0) {
        int tot = 0;
        #pragma unroll
        for (int w = 0; w < 8; w++) tot += red[w];
        g_bsum[blockIdx.x] = tot;
    }
}

// ---------------------------------------------------------------------------
// Scan pass 2: every block scans the block totals (few) + local scan,
// writes exclusive offsets into g_off and g_cur. Block nb-1 writes g_off[n].
// ---------------------------------------------------------------------------
__global__ __launch_bounds__(256) void scan_offsets_kernel(int n, int nb)
{
    __shared__ int sb[257];
    __shared__ int ts[256];
    const int t = threadIdx.x;

    if (t < nb) sb[t] = g_bsum[t];
    __syncthreads();
    if (t == 0) {
        int a = 0;
        for (int b = 0; b < nb; b++) { const int v = sb[b]; sb[b] = a; a += v; }
        sb[nb] = a;
    }
    __syncthreads();

    const int base_excl = sb[blockIdx.x];
    const int idx0 = blockIdx.x * 1024 + t * 4;

    int v[4];
    #pragma unroll
    for (int j = 0; j < 4; j++)
        v[j] = (idx0 + j < n) ? g_cnt[idx0 + j] : 0;
    const int s = v[0] + v[1] + v[2] + v[3];

    ts[t] = s;
    __syncthreads();
    // inclusive Hillis-Steele scan over 256 thread sums
    #pragma unroll
    for (int d = 1; d < 256; d <<= 1) {
        int x = 0;
        if (t >= d) x = ts[t - d];
        __syncthreads();
        ts[t] += x;
        __syncthreads();
    }
    int run = base_excl + ts[t] - s;

    #pragma unroll
    for (int j = 0; j < 4; j++) {
        if (idx0 + j < n) {
            g_off[idx0 + j] = run;
            g_cur[idx0 + j] = run;
            run += v[j];
        }
    }
    if (blockIdx.x == 0 && t == 0) g_off[n] = sb[nb];
}

// ---------------------------------------------------------------------------
// Reorder: scatter (col, dw1[time]) payloads into row-sorted order
// ---------------------------------------------------------------------------
__global__ __launch_bounds__(256) void reorder_kernel(
    const int* __restrict__ erow, const int* __restrict__ ecol,
    const int* __restrict__ etime, const float* __restrict__ dw1, int E)
{
    const int i = blockIdx.x * 256 + threadIdx.x;
    const int e0 = i * 4;
    if (e0 + 3 < E) {
        const int4 r = reinterpret_cast<const int4*>(erow)[i];
        const int4 c = reinterpret_cast<const int4*>(ecol)[i];
        const int4 tt = reinterpret_cast<const int4*>(etime)[i];
        const int p0 = atomicAdd(&g_cur[r.x], 1);
        const int p1 = atomicAdd(&g_cur[r.y], 1);
        const int p2 = atomicAdd(&g_cur[r.z], 1);
        const int p3 = atomicAdd(&g_cur[r.w], 1);
        g_sorted[p0] = (unsigned)c.x |
            ((unsigned long long)__float_as_uint(__ldg(dw1 + tt.x)) << 32);
        g_sorted[p1] = (unsigned)c.y |
            ((unsigned long long)__float_as_uint(__ldg(dw1 + tt.y)) << 32);
        g_sorted[p2] = (unsigned)c.z |
            ((unsigned long long)__float_as_uint(__ldg(dw1 + tt.z)) << 32);
        g_sorted[p3] = (unsigned)c.w |
            ((unsigned long long)__float_as_uint(__ldg(dw1 + tt.w)) << 32);
    } else {
        for (int e = e0; e < E; e++) {
            const int r = erow[e];
            const int p = atomicAdd(&g_cur[r], 1);
            g_sorted[p] = (unsigned)ecol[e] |
                ((unsigned long long)__float_as_uint(__ldg(dw1 + etime[e])) << 32);
        }
    }
}

// ---------------------------------------------------------------------------
// Gather: 8 threads per row; register accumulation, no atomics.
// out[r] = w2[r] * sum_i d_i * h[c_i]
// ---------------------------------------------------------------------------
__global__ __launch_bounds__(256) void gather_kernel(float* __restrict__ out, int n)
{
    const int gid = blockIdx.x * 256 + threadIdx.x;
    const int r = gid >> 3;
    const int p = gid & 7;
    if (r >= n) return;

    const int beg = __ldg(&g_off[r]);
    const int end = __ldg(&g_off[r + 1]);

    float4 acc = make_float4(0.f, 0.f, 0.f, 0.f);

    int i = beg;
    for (; i + 1 < end; i += 2) {
        const unsigned long long pk0 = __ldg(&g_sorted[i]);
        const unsigned long long pk1 = __ldg(&g_sorted[i + 1]);
        const int c0 = (int)(unsigned)pk0;
        const int c1 = (int)(unsigned)pk1;
        const float d0 = __uint_as_float((unsigned)(pk0 >> 32));
        const float d1 = __uint_as_float((unsigned)(pk1 >> 32));
        const float4 v0 = *reinterpret_cast<const float4*>(&g_h[c0 * D_OUT + p * 4]);
        const float4 v1 = *reinterpret_cast<const float4*>(&g_h[c1 * D_OUT + p * 4]);
        acc.x = fmaf(d0, v0.x, acc.x); acc.y = fmaf(d0, v0.y, acc.y);
        acc.z = fmaf(d0, v0.z, acc.z); acc.w = fmaf(d0, v0.w, acc.w);
        acc.x = fmaf(d1, v1.x, acc.x); acc.y = fmaf(d1, v1.y, acc.y);
        acc.z = fmaf(d1, v1.z, acc.z); acc.w = fmaf(d1, v1.w, acc.w);
    }
    if (i < end) {
        const unsigned long long pk = __ldg(&g_sorted[i]);
        const int c = (int)(unsigned)pk;
        const float d = __uint_as_float((unsigned)(pk >> 32));
        const float4 v = *reinterpret_cast<const float4*>(&g_h[c * D_OUT + p * 4]);
        acc.x = fmaf(d, v.x, acc.x); acc.y = fmaf(d, v.y, acc.y);
        acc.z = fmaf(d, v.z, acc.z); acc.w = fmaf(d, v.w, acc.w);
    }

    const float w = __ldg(&g_w2[r]);
    acc.x *= w; acc.y *= w; acc.z *= w; acc.w *= w;
    *reinterpret_cast<float4*>(&out[r * D_OUT + p * 4]) = acc;
}

// ---------------------------------------------------------------------------
extern "C" void kernel_launch(void* const* d_in, const int* in_sizes, int n_in,
                              void* d_out, int out_size)
{
    const float* X    = (const float*)d_in[0];
    const float* W    = (const float*)d_in[1];
    const float* dw1  = (const float*)d_in[2];
    const float* dw2  = (const float*)d_in[3];
    const int*  erow  = (const int*)d_in[4];
    const int*  ecol  = (const int*)d_in[5];
    const int*  etime = (const int*)d_in[6];
    const int*  arrive= (const int*)d_in[7];
    const int*  obs_p = (n_in > 8) ? (const int*)d_in[8] : nullptr;

    const int n = in_sizes[7];
    const int E = in_sizes[4];
    const int nb = (n + 1023) / 1024;

    void* cnt_ptr = nullptr;
    cudaGetSymbolAddress(&cnt_ptr, g_cnt);
    cudaMemsetAsync(cnt_ptr, 0, (size_t)n * sizeof(int));

    // histogram of edge rows
    hist_kernel<<<(E / 4 + 255) / 256 + 1, 256>>>(erow, E);

    // h = relu(X @ W) + w2 precompute
    gemm_relu_kernel<<<(n + 127) / 128, 128>>>(X, W, arrive, dw2, obs_p, n);

    // prefix scan -> g_off / g_cur
    scan_totals_kernel<<<nb, 256>>>(n);
    scan_offsets_kernel<<<nb, 256>>>(n, nb);

    // row-sorted edge payloads
    reorder_kernel<<<(E / 4 + 255) / 256 + 1, 256>>>(erow, ecol, etime, dw1, E);

    // atomic-free gather
    gather_kernel<<<(n * 8 + 255) / 256, 256>>>((float*)d_out, n);
}